// round 14
// baseline (speedup 1.0000x reference)
#include <cuda_runtime.h>
#include <cuda_fp16.h>
#include <math.h>

// Problem constants
#define NV 65536      // nodes
#define NE 131072     // edges
#define NB 2048       // graphs
#define DD 64         // DIM
#define NF 75         // node features
#define EF 16         // edge features
#define H1 128        // mlp hidden
#define D2 4096       // DIM*DIM

// ---------------- scratch (static device arrays; no allocation) ----------------
__device__ __half g_h1[(size_t)NE * H1];                // 33.5 MB (fp16)
__device__ __half g_W[(size_t)NE * D2];                 // 1 GiB (fp16)
__device__ __half g_w2h[(size_t)H1 * D2];               // 1 MB (fp16 mlp_w2)
__device__ float g_x[(size_t)NV * DD];                  // current "out"
__device__ float g_h[(size_t)NV * DD];                  // GRU hidden
__device__ float g_agg[(size_t)NV * DD];                // scatter target
__device__ float g_cnt[NV];                             // in-degree (float)
__device__ int   g_off[NB + 1];                         // graph start offsets
__device__ float g_qstar[NB * 2 * DD];
__device__ float g_hs[NB * DD];
__device__ float g_cs[NB * DD];

// ---------------- zero kernels ----------------
__global__ void zero_cnt_kernel() {
    int i = blockIdx.x * 256 + threadIdx.x;
    if (i < NV) g_cnt[i] = 0.f;
}
__global__ void zero_agg_kernel() {
    size_t i = (size_t)blockIdx.x * 256 + threadIdx.x;
    if (i < (size_t)NV * DD) g_agg[i] = 0.f;
}
__global__ void zero_s2s_kernel() {
    int i = blockIdx.x * 256 + threadIdx.x;
    if (i < NB * 2 * DD) g_qstar[i] = 0.f;
    if (i < NB * DD) { g_hs[i] = 0.f; g_cs[i] = 0.f; }
}

// ---------------- counts + offsets ----------------
__global__ void count_kernel(const int* __restrict__ dst) {
    int e = blockIdx.x * 256 + threadIdx.x;
    if (e < NE) atomicAdd(&g_cnt[dst[e]], 1.f);
}
__global__ void offs_kernel(const int* __restrict__ gidx) {
    int n = blockIdx.x * 256 + threadIdx.x;
    if (n >= NV) return;
    int g = gidx[n];
    int gp = (n == 0) ? -1 : gidx[n - 1];
    for (int b = gp + 1; b <= g; b++) g_off[b] = n;
    if (n == NV - 1) for (int b = g + 1; b <= NB; b++) g_off[b] = NV;
}

// ---------------- lin0: out = relu(nf @ lin0_w + lin0_b) ----------------
__global__ __launch_bounds__(256) void lin0_kernel(
    const float* __restrict__ nf, const float* __restrict__ w, const float* __restrict__ b)
{
    __shared__ float sf[4][NF + 1];
    int tid = threadIdx.x;
    for (int i = tid; i < 4 * NF; i += 256) {
        int nn = blockIdx.x * 4 + i / NF;
        sf[i / NF][i % NF] = nf[(size_t)nn * NF + i % NF];
    }
    __syncthreads();
    int nl = tid >> 6, f = tid & 63;
    size_t n = (size_t)blockIdx.x * 4 + nl;
    float acc = b[f];
    #pragma unroll 5
    for (int k = 0; k < NF; k++) acc = fmaf(sf[nl][k], w[k * DD + f], acc);
    acc = fmaxf(acc, 0.f);
    g_x[n * DD + f] = acc;
    g_h[n * DD + f] = acc;
}

// ---------------- h1 = relu(ef @ mlp_w1 + mlp_b1), stored fp16 ----------------
__global__ __launch_bounds__(256) void h1_kernel(
    const float* __restrict__ ef, const float* __restrict__ w1, const float* __restrict__ b1)
{
    __shared__ float se[2][EF];
    int tid = threadIdx.x;
    if (tid < 32) {
        int ee = blockIdx.x * 2 + tid / EF;
        se[tid / EF][tid % EF] = ef[(size_t)ee * EF + tid % EF];
    }
    __syncthreads();
    int el = tid >> 7, j = tid & 127;
    size_t e = (size_t)blockIdx.x * 2 + el;
    float acc = b1[j];
    #pragma unroll
    for (int k = 0; k < EF; k++) acc = fmaf(se[el][k], w1[k * H1 + j], acc);
    g_h1[e * H1 + j] = __float2half_rn(fmaxf(acc, 0.f));
}

// ---------------- mlp_w2 fp32 -> fp16 (done once) ----------------
__global__ void w2cvt_kernel(const float* __restrict__ w2) {
    size_t i = (size_t)blockIdx.x * 256 + threadIdx.x;
    if (i < (size_t)H1 * D2) g_w2h[i] = __float2half_rn(w2[i]);
}

// ---------------- W GEMM (fp16 tensor cores): W = h1 @ w2 + b2 ----------------
// Block tile 128(M) x 64(N), K=128 staged once. 8 warps: 4(M) x 2(N).
#define WPAD 136
#define BPAD 72
#define WG_SMEM ((128 * WPAD + 128 * BPAD) * 2)   // As + Bs, fp16
__global__ __launch_bounds__(256) void wgemm_f16_kernel(const float* __restrict__ bias)
{
    extern __shared__ __half ws[];
    __half* As = ws;                  // [128][WPAD]
    __half* Bs = ws + 128 * WPAD;     // [128][BPAD] (K rows x 64 N cols)
    int tid = threadIdx.x;
    int warp = tid >> 5, lane = tid & 31;
    int n0 = blockIdx.x * 64;
    size_t m0 = (size_t)blockIdx.y * 128;

    #pragma unroll
    for (int l = 0; l < 8; l++) {
        int idx = l * 256 + tid;
        int row = idx >> 4, ch = idx & 15;
        uint4 v = *(const uint4*)(g_h1 + (m0 + row) * H1 + ch * 8);
        *(uint4*)(As + row * WPAD + ch * 8) = v;
    }
    #pragma unroll
    for (int l = 0; l < 4; l++) {
        int idx = l * 256 + tid;
        int row = idx >> 3, ch = idx & 7;
        *(uint4*)(Bs + row * BPAD + ch * 8) =
            *(const uint4*)(g_w2h + (size_t)row * D2 + n0 + ch * 8);
    }
    __syncthreads();

    int wm = (warp & 3) * 32, wn = (warp >> 2) * 32;
    float acc[2][4][4];
    #pragma unroll
    for (int mi = 0; mi < 2; mi++)
        #pragma unroll
        for (int ni = 0; ni < 4; ni++)
            #pragma unroll
            for (int k = 0; k < 4; k++) acc[mi][ni][k] = 0.f;

    #pragma unroll
    for (int kk = 0; kk < 128; kk += 16) {
        unsigned a[2][4], b[2][4];
        #pragma unroll
        for (int mi = 0; mi < 2; mi++) {
            const __half* ap =
                As + (wm + mi * 16 + (lane & 15)) * WPAD + kk + (lane >> 4) * 8;
            unsigned addr = (unsigned)__cvta_generic_to_shared(ap);
            asm volatile("ldmatrix.sync.aligned.m8n8.x4.shared.b16 {%0,%1,%2,%3}, [%4];"
                : "=r"(a[mi][0]), "=r"(a[mi][1]), "=r"(a[mi][2]), "=r"(a[mi][3])
                : "r"(addr));
        }
        #pragma unroll
        for (int nb = 0; nb < 2; nb++) {
            const __half* bp =
                Bs + (kk + (lane & 7) + ((lane >> 3) & 1) * 8) * BPAD
                   + wn + nb * 16 + (lane >> 4) * 8;
            unsigned addr = (unsigned)__cvta_generic_to_shared(bp);
            asm volatile("ldmatrix.sync.aligned.m8n8.x4.trans.shared.b16 {%0,%1,%2,%3}, [%4];"
                : "=r"(b[nb][0]), "=r"(b[nb][1]), "=r"(b[nb][2]), "=r"(b[nb][3])
                : "r"(addr));
        }
        #pragma unroll
        for (int mi = 0; mi < 2; mi++)
            #pragma unroll
            for (int ni = 0; ni < 4; ni++) {
                unsigned b0 = b[ni >> 1][(ni & 1) * 2];
                unsigned b1 = b[ni >> 1][(ni & 1) * 2 + 1];
                asm volatile(
                    "mma.sync.aligned.m16n8k16.row.col.f32.f16.f16.f32 "
                    "{%0,%1,%2,%3}, {%4,%5,%6,%7}, {%8,%9}, {%0,%1,%2,%3};"
                    : "+f"(acc[mi][ni][0]), "+f"(acc[mi][ni][1]),
                      "+f"(acc[mi][ni][2]), "+f"(acc[mi][ni][3])
                    : "r"(a[mi][0]), "r"(a[mi][1]), "r"(a[mi][2]), "r"(a[mi][3]),
                      "r"(b0), "r"(b1));
            }
    }
    __syncthreads();

    int g = lane >> 2, t4 = lane & 3;
    #pragma unroll
    for (int mi = 0; mi < 2; mi++) {
        int r0 = wm + mi * 16 + g;
        #pragma unroll
        for (int ni = 0; ni < 4; ni++) {
            int c = wn + ni * 8 + t4 * 2;
            float2 bv = *(const float2*)&bias[n0 + c];
            *(__half2*)(As + r0 * WPAD + c) =
                __floats2half2_rn(acc[mi][ni][0] + bv.x, acc[mi][ni][1] + bv.y);
            *(__half2*)(As + (r0 + 8) * WPAD + c) =
                __floats2half2_rn(acc[mi][ni][2] + bv.x, acc[mi][ni][3] + bv.y);
        }
    }
    __syncthreads();
    #pragma unroll
    for (int l = 0; l < 4; l++) {
        int idx = l * 256 + tid;
        int row = idx >> 3, ch = idx & 7;
        *(uint4*)(g_W + (m0 + row) * D2 + n0 + ch * 8) =
            *(const uint4*)(As + row * WPAD + ch * 8);
    }
}

// ---------------- message + scatter: agg[dst] += x[src]^T W[e] (fp16 W) ----------------
__global__ __launch_bounds__(256) void msg_kernel(
    const int* __restrict__ src, const int* __restrict__ dst)
{
    int warp = (blockIdx.x * 256 + threadIdx.x) >> 5;
    int lane = threadIdx.x & 31;
    const __half2* __restrict__ W2 =
        (const __half2*)(g_W + (size_t)warp * D2);
    const float* xs = g_x + (size_t)src[warp] * DD;
    float xv  = xs[lane];
    float xv2 = xs[lane + 32];
    float a0 = 0.f, a1 = 0.f;
    #pragma unroll 8
    for (int d = 0; d < 64; d++) {
        float xd = __shfl_sync(0xffffffffu, (d < 32) ? xv : xv2, d & 31);
        float2 w = __half22float2(W2[d * 32 + lane]);
        a0 = fmaf(xd, w.x, a0);
        a1 = fmaf(xd, w.y, a1);
    }
    float* ag = g_agg + (size_t)dst[warp] * DD;
    atomicAdd(ag + 2 * lane, a0);
    atomicAdd(ag + 2 * lane + 1, a1);
}

// ---------------- fused relu(agg/cnt + bias) + GRU step (split-4 rows) ----------------
// 768 threads: thread = (row 0..191, quarter 0..3). Each thread holds 16
// weight columns of wih/whh row in 8 float4 regs (~56 regs total, no spill).
// 64 nodes per block staged in dynamic smem; quarter partials combined by
// shfl_xor(1),shfl_xor(2) (lanes 4k..4k+3 share a row).
#define GNPB 64
#define GRU_SMEM ((GNPB * 64 * 2 + GNPB * 128 + GNPB * 64 * 2) * 4)   // 96 KB
__global__ __launch_bounds__(768) void gru_kernel(
    const float* __restrict__ cbias,
    const float* __restrict__ wih, const float* __restrict__ whh,
    const float* __restrict__ bih, const float* __restrict__ bhh,
    const float* __restrict__ agg_in, const float* __restrict__ h_in,
    float* __restrict__ h_out, float* __restrict__ x_out,
    float* __restrict__ out_extra)
{
    extern __shared__ float gsm[];
    float* s_m  = gsm;                         // [GNPB][64]
    float* s_h  = gsm + GNPB * 64;             // [GNPB][64]
    float* sg01 = gsm + GNPB * 128;            // [GNPB][128]
    float* sgi2 = gsm + GNPB * 256;            // [GNPB][64]
    float* sgh2 = gsm + GNPB * 320;            // [GNPB][64]
    int t = threadIdx.x;
    int q = t & 3, row = t >> 2;

    float4 w_i[4], w_h[4];
    #pragma unroll
    for (int j = 0; j < 4; j++) {
        w_i[j] = *(const float4*)&wih[row * 64 + q * 16 + j * 4];
        w_h[j] = *(const float4*)&whh[row * 64 + q * 16 + j * 4];
    }
    float bi = (q == 0) ? bih[row] : 0.f;
    float bh = (q == 0) ? bhh[row] : 0.f;
    size_t base = (size_t)blockIdx.x * GNPB;

    // Phase A: stage m = relu(agg/cnt + cbias) and h for GNPB nodes
    for (int i = t; i < GNPB * 64; i += 768) {
        int node = i >> 6, f = i & 63;
        size_t n = base + node;
        float cv = g_cnt[n];
        s_m[node * 64 + f] = fmaxf(agg_in[n * 64 + f] / fmaxf(cv, 1.f) + cbias[f], 0.f);
        s_h[node * 64 + f] = h_in[n * 64 + f];
    }
    __syncthreads();

    // Phase B: per-node gate pre-activations (quarter partials + shfl combine)
    #pragma unroll 8
    for (int node = 0; node < GNPB; node++) {
        float ai = bi, ah = bh;
        const float4* mp = (const float4*)(s_m + node * 64 + q * 16);
        const float4* hp = (const float4*)(s_h + node * 64 + q * 16);
        #pragma unroll
        for (int j = 0; j < 4; j++) {
            float4 mv = mp[j], hv = hp[j];
            ai = fmaf(w_i[j].x, mv.x, ai); ai = fmaf(w_i[j].y, mv.y, ai);
            ai = fmaf(w_i[j].z, mv.z, ai); ai = fmaf(w_i[j].w, mv.w, ai);
            ah = fmaf(w_h[j].x, hv.x, ah); ah = fmaf(w_h[j].y, hv.y, ah);
            ah = fmaf(w_h[j].z, hv.z, ah); ah = fmaf(w_h[j].w, hv.w, ah);
        }
        ai += __shfl_xor_sync(0xffffffffu, ai, 1);
        ai += __shfl_xor_sync(0xffffffffu, ai, 2);
        ah += __shfl_xor_sync(0xffffffffu, ah, 1);
        ah += __shfl_xor_sync(0xffffffffu, ah, 2);
        if (q == 0) {
            if (row < 128) sg01[node * 128 + row] = ai + ah;
            else { sgi2[node * 64 + row - 128] = ai; sgh2[node * 64 + row - 128] = ah; }
        }
    }
    __syncthreads();

    // Phase C: activations + state update
    for (int i = t; i < GNPB * 64; i += 768) {
        int node = i >> 6, f = i & 63;
        size_t n = base + node;
        float r  = 1.f / (1.f + expf(-sg01[node * 128 + f]));
        float z  = 1.f / (1.f + expf(-sg01[node * 128 + 64 + f]));
        float nn = tanhf(sgi2[node * 64 + f] + r * sgh2[node * 64 + f]);
        float hval = s_h[node * 64 + f];
        float hn = (1.f - z) * nn + z * hval;
        h_out[n * 64 + f] = hn;
        x_out[n * 64 + f] = hn;
        if (out_extra) out_extra[n * 64 + f] = hn;
    }
}

// ---------------- Set2Set LSTM step ----------------
__global__ __launch_bounds__(256) void lstm_kernel(
    const float* __restrict__ wih, const float* __restrict__ whh,
    const float* __restrict__ bih, const float* __restrict__ bhh)
{
    int b = blockIdx.x, j = threadIdx.x;
    __shared__ float sq[128], sh[64], sg[256];
    if (j < 128) sq[j] = g_qstar[b * 128 + j];
    if (j < 64)  sh[j] = g_hs[b * 64 + j];
    __syncthreads();
    float acc = bih[j] + bhh[j];
    const float* wi = wih + (size_t)j * 128;
    #pragma unroll
    for (int k = 0; k < 128; k += 4) {
        float4 w = *(const float4*)(wi + k);
        float4 q = *(const float4*)(sq + k);
        acc = fmaf(w.x, q.x, acc); acc = fmaf(w.y, q.y, acc);
        acc = fmaf(w.z, q.z, acc); acc = fmaf(w.w, q.w, acc);
    }
    const float* wh = whh + (size_t)j * 64;
    #pragma unroll
    for (int k = 0; k < 64; k += 4) {
        float4 w = *(const float4*)(wh + k);
        float4 hv = *(const float4*)(sh + k);
        acc = fmaf(w.x, hv.x, acc); acc = fmaf(w.y, hv.y, acc);
        acc = fmaf(w.z, hv.z, acc); acc = fmaf(w.w, hv.w, acc);
    }
    sg[j] = acc;
    __syncthreads();
    if (j < 64) {
        float ig = 1.f / (1.f + expf(-sg[j]));
        float fg = 1.f / (1.f + expf(-sg[64 + j]));
        float gg = tanhf(sg[128 + j]);
        float og = 1.f / (1.f + expf(-sg[192 + j]));
        float c  = fg * g_cs[b * 64 + j] + ig * gg;
        float hn = og * tanhf(c);
        g_cs[b * 64 + j] = c;
        g_hs[b * 64 + j] = hn;
        g_qstar[b * 128 + j] = hn;
    }
}

// ---------------- Set2Set attention (softmax over sorted segments) ----------------
__global__ __launch_bounds__(128) void attn_kernel(float* __restrict__ dout)
{
    int b = blockIdx.x, tid = threadIdx.x;
    __shared__ float sq[64];
    __shared__ float se[2048];
    __shared__ float red[4];
    if (tid < 64) sq[tid] = g_hs[b * 64 + tid];
    __syncthreads();
    int s = g_off[b], e = g_off[b + 1];
    int cnt = e - s; if (cnt > 2048) cnt = 2048;
    float lmax = -3e38f;
    for (int i = tid; i < cnt; i += 128) {
        const float* xr = g_x + (size_t)(s + i) * DD;
        float acc = 0.f;
        #pragma unroll
        for (int d = 0; d < 64; d += 4) {
            float4 xv = *(const float4*)(xr + d);
            acc = fmaf(xv.x, sq[d], acc);     acc = fmaf(xv.y, sq[d + 1], acc);
            acc = fmaf(xv.z, sq[d + 2], acc); acc = fmaf(xv.w, sq[d + 3], acc);
        }
        se[i] = acc;
        lmax = fmaxf(lmax, acc);
    }
    #pragma unroll
    for (int o = 16; o; o >>= 1) lmax = fmaxf(lmax, __shfl_xor_sync(0xffffffffu, lmax, o));
    if ((tid & 31) == 0) red[tid >> 5] = lmax;
    __syncthreads();
    float M = fmaxf(fmaxf(red[0], red[1]), fmaxf(red[2], red[3]));
    __syncthreads();
    float lsum = 0.f;
    for (int i = tid; i < cnt; i += 128) {
        float v = expf(se[i] - M);
        se[i] = v;
        lsum += v;
    }
    #pragma unroll
    for (int o = 16; o; o >>= 1) lsum += __shfl_xor_sync(0xffffffffu, lsum, o);
    if ((tid & 31) == 0) red[tid >> 5] = lsum;
    __syncthreads();
    float S = red[0] + red[1] + red[2] + red[3];
    float inv = 1.f / (S + 1e-16f);
    if (tid < 64) {
        float rv = 0.f;
        for (int i = 0; i < cnt; i++)
            rv = fmaf(se[i], g_x[(size_t)(s + i) * DD + tid], rv);
        rv *= inv;
        g_qstar[b * 128 + 64 + tid] = rv;
        if (dout) {
            dout[b * 128 + tid] = sq[tid];
            dout[b * 128 + 64 + tid] = rv;
        }
    }
}

// ---------------- launch ----------------
extern "C" void kernel_launch(void* const* d_in, const int* in_sizes, int n_in,
                              void* d_out, int out_size)
{
    const float* node_features = (const float*)d_in[0];
    const float* edge_features = (const float*)d_in[1];
    const int*   edge_index    = (const int*)d_in[2];
    const int*   graph_index   = (const int*)d_in[3];
    const float* lin0_w  = (const float*)d_in[4];
    const float* lin0_b  = (const float*)d_in[5];
    const float* mlp_w1  = (const float*)d_in[6];
    const float* mlp_b1  = (const float*)d_in[7];
    const float* mlp_w2  = (const float*)d_in[8];
    const float* mlp_b2  = (const float*)d_in[9];
    const float* conv_bias = (const float*)d_in[10];
    const float* gru_w_ih = (const float*)d_in[11];
    const float* gru_w_hh = (const float*)d_in[12];
    const float* gru_b_ih = (const float*)d_in[13];
    const float* gru_b_hh = (const float*)d_in[14];
    const float* lstm_w_ih = (const float*)d_in[15];
    const float* lstm_w_hh = (const float*)d_in[16];
    const float* lstm_b_ih = (const float*)d_in[17];
    const float* lstm_b_hh = (const float*)d_in[18];
    float* out = (float*)d_out;
    const int* src = edge_index;
    const int* dst = edge_index + NE;

    // Resolve device-global addresses (host API, allocation-free).
    float *p_x = nullptr, *p_h = nullptr, *p_agg = nullptr;
    cudaGetSymbolAddress((void**)&p_x, g_x);
    cudaGetSymbolAddress((void**)&p_h, g_h);
    cudaGetSymbolAddress((void**)&p_agg, g_agg);

    cudaFuncSetAttribute(wgemm_f16_kernel, cudaFuncAttributeMaxDynamicSharedMemorySize, WG_SMEM);
    cudaFuncSetAttribute(gru_kernel, cudaFuncAttributeMaxDynamicSharedMemorySize, GRU_SMEM);

    h1_kernel<<<NE / 2, 256>>>(edge_features, mlp_w1, mlp_b1);
    lin0_kernel<<<NV / 4, 256>>>(node_features, lin0_w, lin0_b);
    zero_cnt_kernel<<<NV / 256, 256>>>();
    w2cvt_kernel<<<(H1 * D2) / 256, 256>>>(mlp_w2);
    dim3 wg(D2 / 64, NE / 128);
    wgemm_f16_kernel<<<wg, 256, WG_SMEM>>>(mlp_b2);
    count_kernel<<<NE / 256, 256>>>(dst);
    offs_kernel<<<NV / 256, 256>>>(graph_index);

    for (int it = 0; it < 3; it++) {
        zero_agg_kernel<<<(NV * DD) / 256, 256>>>();
        msg_kernel<<<NE / 8, 256>>>(src, dst);
        gru_kernel<<<NV / GNPB, 768, GRU_SMEM>>>(conv_bias, gru_w_ih, gru_w_hh,
                                                 gru_b_ih, gru_b_hh,
                                                 p_agg, p_h, p_h, p_x,
                                                 (it == 2) ? (out + NB * 2 * DD) : nullptr);
    }

    zero_s2s_kernel<<<(NB * 2 * DD) / 256, 256>>>();
    for (int t = 0; t < 3; t++) {
        lstm_kernel<<<NB, 256>>>(lstm_w_ih, lstm_w_hh, lstm_b_ih, lstm_b_hh);
        attn_kernel<<<NB, 128>>>((t == 2) ? out : nullptr);
    }
}

// round 15
// speedup vs baseline: 1.2661x; 1.2661x over previous
#include <cuda_runtime.h>
#include <cuda_fp16.h>
#include <math.h>

// Problem constants
#define NV 65536      // nodes
#define NE 131072     // edges
#define NB 2048       // graphs
#define DD 64         // DIM
#define NF 75         // node features
#define EF 16         // edge features
#define H1 128        // mlp hidden
#define D2 4096       // DIM*DIM

// ---------------- scratch (static device arrays; no allocation) ----------------
__device__ __half g_h1[(size_t)NE * H1];                // 33.5 MB (fp16)
__device__ __half g_W[(size_t)NE * D2];                 // 1 GiB (fp16)
__device__ __half g_w2h[(size_t)H1 * D2];               // 1 MB (fp16 mlp_w2)
__device__ float g_x[(size_t)NV * DD];                  // current "out"
__device__ float g_h[(size_t)NV * DD];                  // GRU hidden
__device__ float g_agg[(size_t)NV * DD];                // scatter target
__device__ float g_cnt[NV];                             // in-degree (float)
__device__ int   g_off[NB + 1];                         // graph start offsets
__device__ float g_qstar[NB * 2 * DD];
__device__ float g_hs[NB * DD];
__device__ float g_cs[NB * DD];

// ---------------- zero kernels ----------------
__global__ void zero_cnt_kernel() {
    int i = blockIdx.x * 256 + threadIdx.x;
    if (i < NV) g_cnt[i] = 0.f;
}
__global__ void zero_agg_kernel() {
    size_t i = (size_t)blockIdx.x * 256 + threadIdx.x;
    if (i < (size_t)NV * DD) g_agg[i] = 0.f;
}
__global__ void zero_s2s_kernel() {
    int i = blockIdx.x * 256 + threadIdx.x;
    if (i < NB * 2 * DD) g_qstar[i] = 0.f;
    if (i < NB * DD) { g_hs[i] = 0.f; g_cs[i] = 0.f; }
}

// ---------------- counts + offsets ----------------
__global__ void count_kernel(const int* __restrict__ dst) {
    int e = blockIdx.x * 256 + threadIdx.x;
    if (e < NE) atomicAdd(&g_cnt[dst[e]], 1.f);
}
__global__ void offs_kernel(const int* __restrict__ gidx) {
    int n = blockIdx.x * 256 + threadIdx.x;
    if (n >= NV) return;
    int g = gidx[n];
    int gp = (n == 0) ? -1 : gidx[n - 1];
    for (int b = gp + 1; b <= g; b++) g_off[b] = n;
    if (n == NV - 1) for (int b = g + 1; b <= NB; b++) g_off[b] = NV;
}

// ---------------- lin0: out = relu(nf @ lin0_w + lin0_b) ----------------
__global__ __launch_bounds__(256) void lin0_kernel(
    const float* __restrict__ nf, const float* __restrict__ w, const float* __restrict__ b)
{
    __shared__ float sf[4][NF + 1];
    int tid = threadIdx.x;
    for (int i = tid; i < 4 * NF; i += 256) {
        int nn = blockIdx.x * 4 + i / NF;
        sf[i / NF][i % NF] = nf[(size_t)nn * NF + i % NF];
    }
    __syncthreads();
    int nl = tid >> 6, f = tid & 63;
    size_t n = (size_t)blockIdx.x * 4 + nl;
    float acc = b[f];
    #pragma unroll 5
    for (int k = 0; k < NF; k++) acc = fmaf(sf[nl][k], w[k * DD + f], acc);
    acc = fmaxf(acc, 0.f);
    g_x[n * DD + f] = acc;
    g_h[n * DD + f] = acc;
}

// ---------------- h1 = relu(ef @ mlp_w1 + mlp_b1), stored fp16 ----------------
__global__ __launch_bounds__(256) void h1_kernel(
    const float* __restrict__ ef, const float* __restrict__ w1, const float* __restrict__ b1)
{
    __shared__ float se[2][EF];
    int tid = threadIdx.x;
    if (tid < 32) {
        int ee = blockIdx.x * 2 + tid / EF;
        se[tid / EF][tid % EF] = ef[(size_t)ee * EF + tid % EF];
    }
    __syncthreads();
    int el = tid >> 7, j = tid & 127;
    size_t e = (size_t)blockIdx.x * 2 + el;
    float acc = b1[j];
    #pragma unroll
    for (int k = 0; k < EF; k++) acc = fmaf(se[el][k], w1[k * H1 + j], acc);
    g_h1[e * H1 + j] = __float2half_rn(fmaxf(acc, 0.f));
}

// ---------------- mlp_w2 fp32 -> fp16 (done once) ----------------
__global__ void w2cvt_kernel(const float* __restrict__ w2) {
    size_t i = (size_t)blockIdx.x * 256 + threadIdx.x;
    if (i < (size_t)H1 * D2) g_w2h[i] = __float2half_rn(w2[i]);
}

// ---------------- W GEMM (fp16 tensor cores): W = h1 @ w2 + b2 ----------------
// Block tile 128(M) x 64(N), K=128 staged once. 8 warps: 4(M) x 2(N).
#define WPAD 136
#define BPAD 72
#define WG_SMEM ((128 * WPAD + 128 * BPAD) * 2)   // As + Bs, fp16
__global__ __launch_bounds__(256) void wgemm_f16_kernel(const float* __restrict__ bias)
{
    extern __shared__ __half ws[];
    __half* As = ws;                  // [128][WPAD]
    __half* Bs = ws + 128 * WPAD;     // [128][BPAD] (K rows x 64 N cols)
    int tid = threadIdx.x;
    int warp = tid >> 5, lane = tid & 31;
    int n0 = blockIdx.x * 64;
    size_t m0 = (size_t)blockIdx.y * 128;

    #pragma unroll
    for (int l = 0; l < 8; l++) {
        int idx = l * 256 + tid;
        int row = idx >> 4, ch = idx & 15;
        uint4 v = *(const uint4*)(g_h1 + (m0 + row) * H1 + ch * 8);
        *(uint4*)(As + row * WPAD + ch * 8) = v;
    }
    #pragma unroll
    for (int l = 0; l < 4; l++) {
        int idx = l * 256 + tid;
        int row = idx >> 3, ch = idx & 7;
        *(uint4*)(Bs + row * BPAD + ch * 8) =
            *(const uint4*)(g_w2h + (size_t)row * D2 + n0 + ch * 8);
    }
    __syncthreads();

    int wm = (warp & 3) * 32, wn = (warp >> 2) * 32;
    float acc[2][4][4];
    #pragma unroll
    for (int mi = 0; mi < 2; mi++)
        #pragma unroll
        for (int ni = 0; ni < 4; ni++)
            #pragma unroll
            for (int k = 0; k < 4; k++) acc[mi][ni][k] = 0.f;

    #pragma unroll
    for (int kk = 0; kk < 128; kk += 16) {
        unsigned a[2][4], b[2][4];
        #pragma unroll
        for (int mi = 0; mi < 2; mi++) {
            const __half* ap =
                As + (wm + mi * 16 + (lane & 15)) * WPAD + kk + (lane >> 4) * 8;
            unsigned addr = (unsigned)__cvta_generic_to_shared(ap);
            asm volatile("ldmatrix.sync.aligned.m8n8.x4.shared.b16 {%0,%1,%2,%3}, [%4];"
                : "=r"(a[mi][0]), "=r"(a[mi][1]), "=r"(a[mi][2]), "=r"(a[mi][3])
                : "r"(addr));
        }
        #pragma unroll
        for (int nb = 0; nb < 2; nb++) {
            const __half* bp =
                Bs + (kk + (lane & 7) + ((lane >> 3) & 1) * 8) * BPAD
                   + wn + nb * 16 + (lane >> 4) * 8;
            unsigned addr = (unsigned)__cvta_generic_to_shared(bp);
            asm volatile("ldmatrix.sync.aligned.m8n8.x4.trans.shared.b16 {%0,%1,%2,%3}, [%4];"
                : "=r"(b[nb][0]), "=r"(b[nb][1]), "=r"(b[nb][2]), "=r"(b[nb][3])
                : "r"(addr));
        }
        #pragma unroll
        for (int mi = 0; mi < 2; mi++)
            #pragma unroll
            for (int ni = 0; ni < 4; ni++) {
                unsigned b0 = b[ni >> 1][(ni & 1) * 2];
                unsigned b1 = b[ni >> 1][(ni & 1) * 2 + 1];
                asm volatile(
                    "mma.sync.aligned.m16n8k16.row.col.f32.f16.f16.f32 "
                    "{%0,%1,%2,%3}, {%4,%5,%6,%7}, {%8,%9}, {%0,%1,%2,%3};"
                    : "+f"(acc[mi][ni][0]), "+f"(acc[mi][ni][1]),
                      "+f"(acc[mi][ni][2]), "+f"(acc[mi][ni][3])
                    : "r"(a[mi][0]), "r"(a[mi][1]), "r"(a[mi][2]), "r"(a[mi][3]),
                      "r"(b0), "r"(b1));
            }
    }
    __syncthreads();

    int g = lane >> 2, t4 = lane & 3;
    #pragma unroll
    for (int mi = 0; mi < 2; mi++) {
        int r0 = wm + mi * 16 + g;
        #pragma unroll
        for (int ni = 0; ni < 4; ni++) {
            int c = wn + ni * 8 + t4 * 2;
            float2 bv = *(const float2*)&bias[n0 + c];
            *(__half2*)(As + r0 * WPAD + c) =
                __floats2half2_rn(acc[mi][ni][0] + bv.x, acc[mi][ni][1] + bv.y);
            *(__half2*)(As + (r0 + 8) * WPAD + c) =
                __floats2half2_rn(acc[mi][ni][2] + bv.x, acc[mi][ni][3] + bv.y);
        }
    }
    __syncthreads();
    #pragma unroll
    for (int l = 0; l < 4; l++) {
        int idx = l * 256 + tid;
        int row = idx >> 3, ch = idx & 7;
        *(uint4*)(g_W + (m0 + row) * D2 + n0 + ch * 8) =
            *(const uint4*)(As + row * WPAD + ch * 8);
    }
}

// ---------------- message + scatter: agg[dst] += x[src]^T W[e] (fp16 W) ----------------
__global__ __launch_bounds__(256) void msg_kernel(
    const int* __restrict__ src, const int* __restrict__ dst)
{
    int warp = (blockIdx.x * 256 + threadIdx.x) >> 5;
    int lane = threadIdx.x & 31;
    const __half2* __restrict__ W2 =
        (const __half2*)(g_W + (size_t)warp * D2);
    const float* xs = g_x + (size_t)src[warp] * DD;
    float xv  = xs[lane];
    float xv2 = xs[lane + 32];
    float a0 = 0.f, a1 = 0.f;
    #pragma unroll 8
    for (int d = 0; d < 64; d++) {
        float xd = __shfl_sync(0xffffffffu, (d < 32) ? xv : xv2, d & 31);
        float2 w = __half22float2(W2[d * 32 + lane]);
        a0 = fmaf(xd, w.x, a0);
        a1 = fmaf(xd, w.y, a1);
    }
    float* ag = g_agg + (size_t)dst[warp] * DD;
    atomicAdd(ag + 2 * lane, a0);
    atomicAdd(ag + 2 * lane + 1, a1);
}

// ---------------- fused relu(agg/cnt + bias) + GRU step (v2, 128 nodes/block) ----------------
// Thread j (0..191) owns gate-row j with its wih/whh rows in REGISTERS
// (zero shfl, zero weight smem traffic). 128 nodes per block -> grid 512
// -> 2 resident blocks/SM (12 warps) for latency hiding.
#define GRUB 8
#define GNPB 128
__global__ __launch_bounds__(192, 2) void gru_kernel(
    const float* __restrict__ cbias,
    const float* __restrict__ wih, const float* __restrict__ whh,
    const float* __restrict__ bih, const float* __restrict__ bhh,
    const float* __restrict__ agg_in, const float* __restrict__ h_in,
    float* __restrict__ h_out, float* __restrict__ x_out,
    float* __restrict__ out_extra)
{
    __shared__ float s_m[GRUB][64], s_h[GRUB][64];
    __shared__ float sg01[GRUB][128];     // r,z pre-activations
    __shared__ float sgi2[GRUB][64], sgh2[GRUB][64];
    int t = threadIdx.x;                  // gate row j = t
    float4 w_i[16], w_h[16];
    #pragma unroll
    for (int q = 0; q < 16; q++) {
        w_i[q] = *(const float4*)&wih[t * 64 + q * 4];
        w_h[q] = *(const float4*)&whh[t * 64 + q * 4];
    }
    float bi = bih[t], bh = bhh[t];
    size_t base = (size_t)blockIdx.x * GNPB;

    for (int nb = 0; nb < GNPB; nb += GRUB) {
        __syncthreads();   // protect smem reuse from previous combine phase
        for (int i = t; i < GRUB * 64; i += 192) {
            int node = i >> 6, f = i & 63;
            size_t n = base + nb + node;
            float cv = g_cnt[n];
            s_m[node][f] = fmaxf(agg_in[n * 64 + f] / fmaxf(cv, 1.f) + cbias[f], 0.f);
            s_h[node][f] = h_in[n * 64 + f];
        }
        __syncthreads();
        #pragma unroll
        for (int node = 0; node < GRUB; node++) {
            float ai = bi, ah = bh;
            const float4* mp = (const float4*)s_m[node];
            const float4* hp = (const float4*)s_h[node];
            #pragma unroll
            for (int q = 0; q < 16; q++) {
                float4 mv = mp[q], hv = hp[q];
                ai = fmaf(w_i[q].x, mv.x, ai); ai = fmaf(w_i[q].y, mv.y, ai);
                ai = fmaf(w_i[q].z, mv.z, ai); ai = fmaf(w_i[q].w, mv.w, ai);
                ah = fmaf(w_h[q].x, hv.x, ah); ah = fmaf(w_h[q].y, hv.y, ah);
                ah = fmaf(w_h[q].z, hv.z, ah); ah = fmaf(w_h[q].w, hv.w, ah);
            }
            if (t < 128) sg01[node][t] = ai + ah;
            else { sgi2[node][t - 128] = ai; sgh2[node][t - 128] = ah; }
        }
        __syncthreads();
        for (int i = t; i < GRUB * 64; i += 192) {
            int node = i >> 6, f = i & 63;
            size_t n = base + nb + node;
            float r  = 1.f / (1.f + expf(-sg01[node][f]));
            float z  = 1.f / (1.f + expf(-sg01[node][64 + f]));
            float nn = tanhf(sgi2[node][f] + r * sgh2[node][f]);
            float hval = s_h[node][f];
            float hn = (1.f - z) * nn + z * hval;
            h_out[n * 64 + f] = hn;
            x_out[n * 64 + f] = hn;
            if (out_extra) out_extra[n * 64 + f] = hn;
        }
    }
}

// ---------------- Set2Set LSTM step ----------------
__global__ __launch_bounds__(256) void lstm_kernel(
    const float* __restrict__ wih, const float* __restrict__ whh,
    const float* __restrict__ bih, const float* __restrict__ bhh)
{
    int b = blockIdx.x, j = threadIdx.x;
    __shared__ float sq[128], sh[64], sg[256];
    if (j < 128) sq[j] = g_qstar[b * 128 + j];
    if (j < 64)  sh[j] = g_hs[b * 64 + j];
    __syncthreads();
    float acc = bih[j] + bhh[j];
    const float* wi = wih + (size_t)j * 128;
    #pragma unroll
    for (int k = 0; k < 128; k += 4) {
        float4 w = *(const float4*)(wi + k);
        float4 q = *(const float4*)(sq + k);
        acc = fmaf(w.x, q.x, acc); acc = fmaf(w.y, q.y, acc);
        acc = fmaf(w.z, q.z, acc); acc = fmaf(w.w, q.w, acc);
    }
    const float* wh = whh + (size_t)j * 64;
    #pragma unroll
    for (int k = 0; k < 64; k += 4) {
        float4 w = *(const float4*)(wh + k);
        float4 hv = *(const float4*)(sh + k);
        acc = fmaf(w.x, hv.x, acc); acc = fmaf(w.y, hv.y, acc);
        acc = fmaf(w.z, hv.z, acc); acc = fmaf(w.w, hv.w, acc);
    }
    sg[j] = acc;
    __syncthreads();
    if (j < 64) {
        float ig = 1.f / (1.f + expf(-sg[j]));
        float fg = 1.f / (1.f + expf(-sg[64 + j]));
        float gg = tanhf(sg[128 + j]);
        float og = 1.f / (1.f + expf(-sg[192 + j]));
        float c  = fg * g_cs[b * 64 + j] + ig * gg;
        float hn = og * tanhf(c);
        g_cs[b * 64 + j] = c;
        g_hs[b * 64 + j] = hn;
        g_qstar[b * 128 + j] = hn;
    }
}

// ---------------- Set2Set attention (softmax over sorted segments) ----------------
__global__ __launch_bounds__(128) void attn_kernel(float* __restrict__ dout)
{
    int b = blockIdx.x, tid = threadIdx.x;
    __shared__ float sq[64];
    __shared__ float se[2048];
    __shared__ float red[4];
    if (tid < 64) sq[tid] = g_hs[b * 64 + tid];
    __syncthreads();
    int s = g_off[b], e = g_off[b + 1];
    int cnt = e - s; if (cnt > 2048) cnt = 2048;
    float lmax = -3e38f;
    for (int i = tid; i < cnt; i += 128) {
        const float* xr = g_x + (size_t)(s + i) * DD;
        float acc = 0.f;
        #pragma unroll
        for (int d = 0; d < 64; d += 4) {
            float4 xv = *(const float4*)(xr + d);
            acc = fmaf(xv.x, sq[d], acc);     acc = fmaf(xv.y, sq[d + 1], acc);
            acc = fmaf(xv.z, sq[d + 2], acc); acc = fmaf(xv.w, sq[d + 3], acc);
        }
        se[i] = acc;
        lmax = fmaxf(lmax, acc);
    }
    #pragma unroll
    for (int o = 16; o; o >>= 1) lmax = fmaxf(lmax, __shfl_xor_sync(0xffffffffu, lmax, o));
    if ((tid & 31) == 0) red[tid >> 5] = lmax;
    __syncthreads();
    float M = fmaxf(fmaxf(red[0], red[1]), fmaxf(red[2], red[3]));
    __syncthreads();
    float lsum = 0.f;
    for (int i = tid; i < cnt; i += 128) {
        float v = expf(se[i] - M);
        se[i] = v;
        lsum += v;
    }
    #pragma unroll
    for (int o = 16; o; o >>= 1) lsum += __shfl_xor_sync(0xffffffffu, lsum, o);
    if ((tid & 31) == 0) red[tid >> 5] = lsum;
    __syncthreads();
    float S = red[0] + red[1] + red[2] + red[3];
    float inv = 1.f / (S + 1e-16f);
    if (tid < 64) {
        float rv = 0.f;
        for (int i = 0; i < cnt; i++)
            rv = fmaf(se[i], g_x[(size_t)(s + i) * DD + tid], rv);
        rv *= inv;
        g_qstar[b * 128 + 64 + tid] = rv;
        if (dout) {
            dout[b * 128 + tid] = sq[tid];
            dout[b * 128 + 64 + tid] = rv;
        }
    }
}

// ---------------- launch ----------------
extern "C" void kernel_launch(void* const* d_in, const int* in_sizes, int n_in,
                              void* d_out, int out_size)
{
    const float* node_features = (const float*)d_in[0];
    const float* edge_features = (const float*)d_in[1];
    const int*   edge_index    = (const int*)d_in[2];
    const int*   graph_index   = (const int*)d_in[3];
    const float* lin0_w  = (const float*)d_in[4];
    const float* lin0_b  = (const float*)d_in[5];
    const float* mlp_w1  = (const float*)d_in[6];
    const float* mlp_b1  = (const float*)d_in[7];
    const float* mlp_w2  = (const float*)d_in[8];
    const float* mlp_b2  = (const float*)d_in[9];
    const float* conv_bias = (const float*)d_in[10];
    const float* gru_w_ih = (const float*)d_in[11];
    const float* gru_w_hh = (const float*)d_in[12];
    const float* gru_b_ih = (const float*)d_in[13];
    const float* gru_b_hh = (const float*)d_in[14];
    const float* lstm_w_ih = (const float*)d_in[15];
    const float* lstm_w_hh = (const float*)d_in[16];
    const float* lstm_b_ih = (const float*)d_in[17];
    const float* lstm_b_hh = (const float*)d_in[18];
    float* out = (float*)d_out;
    const int* src = edge_index;
    const int* dst = edge_index + NE;

    // Resolve device-global addresses (host API, allocation-free).
    float *p_x = nullptr, *p_h = nullptr, *p_agg = nullptr;
    cudaGetSymbolAddress((void**)&p_x, g_x);
    cudaGetSymbolAddress((void**)&p_h, g_h);
    cudaGetSymbolAddress((void**)&p_agg, g_agg);

    cudaFuncSetAttribute(wgemm_f16_kernel, cudaFuncAttributeMaxDynamicSharedMemorySize, WG_SMEM);

    h1_kernel<<<NE / 2, 256>>>(edge_features, mlp_w1, mlp_b1);
    lin0_kernel<<<NV / 4, 256>>>(node_features, lin0_w, lin0_b);
    zero_cnt_kernel<<<NV / 256, 256>>>();
    w2cvt_kernel<<<(H1 * D2) / 256, 256>>>(mlp_w2);
    dim3 wg(D2 / 64, NE / 128);
    wgemm_f16_kernel<<<wg, 256, WG_SMEM>>>(mlp_b2);
    count_kernel<<<NE / 256, 256>>>(dst);
    offs_kernel<<<NV / 256, 256>>>(graph_index);

    for (int it = 0; it < 3; it++) {
        zero_agg_kernel<<<(NV * DD) / 256, 256>>>();
        msg_kernel<<<NE / 8, 256>>>(src, dst);
        gru_kernel<<<NV / GNPB, 192>>>(conv_bias, gru_w_ih, gru_w_hh,
                                       gru_b_ih, gru_b_hh,
                                       p_agg, p_h, p_h, p_x,
                                       (it == 2) ? (out + NB * 2 * DD) : nullptr);
    }

    zero_s2s_kernel<<<(NB * 2 * DD) / 256, 256>>>();
    for (int t = 0; t < 3; t++) {
        lstm_kernel<<<NB, 256>>>(lstm_w_ih, lstm_w_hh, lstm_b_ih, lstm_b_hh);
        attn_kernel<<<NB, 128>>>((t == 2) ? out : nullptr);
    }
}

// round 17
// speedup vs baseline: 1.6186x; 1.2785x over previous
#include <cuda_runtime.h>
#include <cuda_fp16.h>
#include <math.h>

// Problem constants
#define NV 65536      // nodes
#define NE 131072     // edges
#define NB 2048       // graphs
#define DD 64         // DIM
#define NF 75         // node features
#define EF 16         // edge features
#define H1 128        // mlp hidden
#define D2 4096       // DIM*DIM

// ---------------- scratch (static device arrays; no allocation) ----------------
__device__ __half g_h1[(size_t)NE * H1];                // 33.5 MB (fp16)
__device__ __half g_W[(size_t)NE * D2];                 // 1 GiB (fp16)
__device__ __half g_w2h[(size_t)H1 * D2];               // 1 MB (fp16 mlp_w2)
__device__ __half g_wcat[128 * 256];                    // fused GRU weights (fp16)
__device__ float g_x[(size_t)NV * DD];                  // current "out"
__device__ float g_h[(size_t)NV * DD];                  // GRU hidden
__device__ float g_agg[(size_t)NV * DD];                // scatter target
__device__ float g_cnt[NV];                             // in-degree (float)
__device__ int   g_off[NB + 1];                         // graph start offsets
__device__ float g_qstar[NB * 2 * DD];
__device__ float g_hs[NB * DD];
__device__ float g_cs[NB * DD];

// ---------------- zero kernels ----------------
__global__ void zero_cnt_kernel() {
    int i = blockIdx.x * 256 + threadIdx.x;
    if (i < NV) g_cnt[i] = 0.f;
}
__global__ void zero_agg_kernel() {
    size_t i = (size_t)blockIdx.x * 256 + threadIdx.x;
    if (i < (size_t)NV * DD) g_agg[i] = 0.f;
}
__global__ void zero_s2s_kernel() {
    int i = blockIdx.x * 256 + threadIdx.x;
    if (i < NB * 2 * DD) g_qstar[i] = 0.f;
    if (i < NB * DD) { g_hs[i] = 0.f; g_cs[i] = 0.f; }
}

// ---------------- counts + offsets ----------------
__global__ void count_kernel(const int* __restrict__ dst) {
    int e = blockIdx.x * 256 + threadIdx.x;
    if (e < NE) atomicAdd(&g_cnt[dst[e]], 1.f);
}
__global__ void offs_kernel(const int* __restrict__ gidx) {
    int n = blockIdx.x * 256 + threadIdx.x;
    if (n >= NV) return;
    int g = gidx[n];
    int gp = (n == 0) ? -1 : gidx[n - 1];
    for (int b = gp + 1; b <= g; b++) g_off[b] = n;
    if (n == NV - 1) for (int b = g + 1; b <= NB; b++) g_off[b] = NV;
}

// ---------------- lin0: out = relu(nf @ lin0_w + lin0_b) ----------------
__global__ __launch_bounds__(256) void lin0_kernel(
    const float* __restrict__ nf, const float* __restrict__ w, const float* __restrict__ b)
{
    __shared__ float sf[4][NF + 1];
    int tid = threadIdx.x;
    for (int i = tid; i < 4 * NF; i += 256) {
        int nn = blockIdx.x * 4 + i / NF;
        sf[i / NF][i % NF] = nf[(size_t)nn * NF + i % NF];
    }
    __syncthreads();
    int nl = tid >> 6, f = tid & 63;
    size_t n = (size_t)blockIdx.x * 4 + nl;
    float acc = b[f];
    #pragma unroll 5
    for (int k = 0; k < NF; k++) acc = fmaf(sf[nl][k], w[k * DD + f], acc);
    acc = fmaxf(acc, 0.f);
    g_x[n * DD + f] = acc;
    g_h[n * DD + f] = acc;
}

// ---------------- h1 = relu(ef @ mlp_w1 + mlp_b1), stored fp16 ----------------
__global__ __launch_bounds__(256) void h1_kernel(
    const float* __restrict__ ef, const float* __restrict__ w1, const float* __restrict__ b1)
{
    __shared__ float se[2][EF];
    int tid = threadIdx.x;
    if (tid < 32) {
        int ee = blockIdx.x * 2 + tid / EF;
        se[tid / EF][tid % EF] = ef[(size_t)ee * EF + tid % EF];
    }
    __syncthreads();
    int el = tid >> 7, j = tid & 127;
    size_t e = (size_t)blockIdx.x * 2 + el;
    float acc = b1[j];
    #pragma unroll
    for (int k = 0; k < EF; k++) acc = fmaf(se[el][k], w1[k * H1 + j], acc);
    g_h1[e * H1 + j] = __float2half_rn(fmaxf(acc, 0.f));
}

// ---------------- mlp_w2 fp32 -> fp16 (done once) ----------------
__global__ void w2cvt_kernel(const float* __restrict__ w2) {
    size_t i = (size_t)blockIdx.x * 256 + threadIdx.x;
    if (i < (size_t)H1 * D2) g_w2h[i] = __float2half_rn(w2[i]);
}

// ---------------- Wcat build: fused GRU weight matrix [K=128][N=256], fp16 ----
// n in [0,128): gates r,z row j=n      : k<64 -> wih[j][k], k>=64 -> whh[j][k-64]
// n in [128,192): gi2 row j=128+(n-128): k<64 -> wih[j][k], k>=64 -> 0
// n in [192,256): gh2 row j=128+(n-192): k<64 -> 0,         k>=64 -> whh[j][k-64]
__global__ void wcat_kernel(const float* __restrict__ wih, const float* __restrict__ whh) {
    int i = blockIdx.x * 256 + threadIdx.x;   // 32768 entries
    int k = i >> 8, n = i & 255;
    float v;
    if (n < 128) {
        v = (k < 64) ? wih[n * 64 + k] : whh[n * 64 + (k - 64)];
    } else if (n < 192) {
        int j = 128 + (n - 128);
        v = (k < 64) ? wih[j * 64 + k] : 0.f;
    } else {
        int j = 128 + (n - 192);
        v = (k < 64) ? 0.f : whh[j * 64 + (k - 64)];
    }
    g_wcat[k * 256 + n] = __float2half_rn(v);
}

// ---------------- W GEMM (fp16 tensor cores): W = h1 @ w2 + b2 ----------------
// Block tile 128(M) x 64(N), K=128 staged once. 8 warps: 4(M) x 2(N).
#define WPAD 136
#define BPAD 72
#define WG_SMEM ((128 * WPAD + 128 * BPAD) * 2)   // As + Bs, fp16
__global__ __launch_bounds__(256) void wgemm_f16_kernel(const float* __restrict__ bias)
{
    extern __shared__ __half ws[];
    __half* As = ws;                  // [128][WPAD]
    __half* Bs = ws + 128 * WPAD;     // [128][BPAD] (K rows x 64 N cols)
    int tid = threadIdx.x;
    int warp = tid >> 5, lane = tid & 31;
    int n0 = blockIdx.x * 64;
    size_t m0 = (size_t)blockIdx.y * 128;

    // stage A: 128 rows x 16 chunks of 8 halfs = 2048
    #pragma unroll
    for (int l = 0; l < 8; l++) {
        int idx = l * 256 + tid;
        int row = idx >> 4, ch = idx & 15;
        uint4 v = *(const uint4*)(g_h1 + (m0 + row) * H1 + ch * 8);
        *(uint4*)(As + row * WPAD + ch * 8) = v;
    }
    // stage B: 128 rows x 8 chunks of 8 halfs = 1024
    #pragma unroll
    for (int l = 0; l < 4; l++) {
        int idx = l * 256 + tid;
        int row = idx >> 3, ch = idx & 7;
        *(uint4*)(Bs + row * BPAD + ch * 8) =
            *(const uint4*)(g_w2h + (size_t)row * D2 + n0 + ch * 8);
    }
    __syncthreads();

    int wm = (warp & 3) * 32, wn = (warp >> 2) * 32;
    float acc[2][4][4];
    #pragma unroll
    for (int mi = 0; mi < 2; mi++)
        #pragma unroll
        for (int ni = 0; ni < 4; ni++)
            #pragma unroll
            for (int k = 0; k < 4; k++) acc[mi][ni][k] = 0.f;

    #pragma unroll
    for (int kk = 0; kk < 128; kk += 16) {
        unsigned a[2][4], b[2][4];
        #pragma unroll
        for (int mi = 0; mi < 2; mi++) {
            const __half* ap =
                As + (wm + mi * 16 + (lane & 15)) * WPAD + kk + (lane >> 4) * 8;
            unsigned addr = (unsigned)__cvta_generic_to_shared(ap);
            asm volatile("ldmatrix.sync.aligned.m8n8.x4.shared.b16 {%0,%1,%2,%3}, [%4];"
                : "=r"(a[mi][0]), "=r"(a[mi][1]), "=r"(a[mi][2]), "=r"(a[mi][3])
                : "r"(addr));
        }
        #pragma unroll
        for (int nb = 0; nb < 2; nb++) {
            const __half* bp =
                Bs + (kk + (lane & 7) + ((lane >> 3) & 1) * 8) * BPAD
                   + wn + nb * 16 + (lane >> 4) * 8;
            unsigned addr = (unsigned)__cvta_generic_to_shared(bp);
            asm volatile("ldmatrix.sync.aligned.m8n8.x4.trans.shared.b16 {%0,%1,%2,%3}, [%4];"
                : "=r"(b[nb][0]), "=r"(b[nb][1]), "=r"(b[nb][2]), "=r"(b[nb][3])
                : "r"(addr));
        }
        #pragma unroll
        for (int mi = 0; mi < 2; mi++)
            #pragma unroll
            for (int ni = 0; ni < 4; ni++) {
                unsigned b0 = b[ni >> 1][(ni & 1) * 2];
                unsigned b1 = b[ni >> 1][(ni & 1) * 2 + 1];
                asm volatile(
                    "mma.sync.aligned.m16n8k16.row.col.f32.f16.f16.f32 "
                    "{%0,%1,%2,%3}, {%4,%5,%6,%7}, {%8,%9}, {%0,%1,%2,%3};"
                    : "+f"(acc[mi][ni][0]), "+f"(acc[mi][ni][1]),
                      "+f"(acc[mi][ni][2]), "+f"(acc[mi][ni][3])
                    : "r"(a[mi][0]), "r"(a[mi][1]), "r"(a[mi][2]), "r"(a[mi][3]),
                      "r"(b0), "r"(b1));
            }
    }
    __syncthreads();

    int g = lane >> 2, t4 = lane & 3;
    #pragma unroll
    for (int mi = 0; mi < 2; mi++) {
        int r0 = wm + mi * 16 + g;
        #pragma unroll
        for (int ni = 0; ni < 4; ni++) {
            int c = wn + ni * 8 + t4 * 2;
            float2 bv = *(const float2*)&bias[n0 + c];
            *(__half2*)(As + r0 * WPAD + c) =
                __floats2half2_rn(acc[mi][ni][0] + bv.x, acc[mi][ni][1] + bv.y);
            *(__half2*)(As + (r0 + 8) * WPAD + c) =
                __floats2half2_rn(acc[mi][ni][2] + bv.x, acc[mi][ni][3] + bv.y);
        }
    }
    __syncthreads();
    // copy out 128x64 fp16 tile: 128 rows x 8 chunks = 1024
    #pragma unroll
    for (int l = 0; l < 4; l++) {
        int idx = l * 256 + tid;
        int row = idx >> 3, ch = idx & 7;
        *(uint4*)(g_W + (m0 + row) * D2 + n0 + ch * 8) =
            *(const uint4*)(As + row * WPAD + ch * 8);
    }
}

// ---------------- message + scatter: agg[dst] += x[src]^T W[e] (fp16 W) ----------------
__global__ __launch_bounds__(256) void msg_kernel(
    const int* __restrict__ src, const int* __restrict__ dst)
{
    int warp = (blockIdx.x * 256 + threadIdx.x) >> 5;
    int lane = threadIdx.x & 31;
    const __half2* __restrict__ W2 =
        (const __half2*)(g_W + (size_t)warp * D2);
    const float* xs = g_x + (size_t)src[warp] * DD;
    float xv  = xs[lane];
    float xv2 = xs[lane + 32];
    float a0 = 0.f, a1 = 0.f;
    #pragma unroll 8
    for (int d = 0; d < 64; d++) {
        float xd = __shfl_sync(0xffffffffu, (d < 32) ? xv : xv2, d & 31);
        float2 w = __half22float2(W2[d * 32 + lane]);
        a0 = fmaf(xd, w.x, a0);
        a1 = fmaf(xd, w.y, a1);
    }
    float* ag = g_agg + (size_t)dst[warp] * DD;
    atomicAdd(ag + 2 * lane, a0);
    atomicAdd(ag + 2 * lane + 1, a1);
}

// ---------------- GRU v4: tensor-core GEMM [m|h] @ Wcat^T + activations ------
// 64 nodes/block, 512 threads (16 warps, 2M x 8N, warp tile 32x32).
// smem: s_in [64][IPAD] fp16 input tile; s_w [128][GPAD] fp16 Wcat;
// s_out (fp32 [64][OPAD]) aliases s_w after the MMA loop.
#define IPAD 136
#define GPAD 264
#define OPAD 260
#define GRU_SMEM (64 * IPAD * 2 + 128 * GPAD * 2)   // 84992 B
__global__ __launch_bounds__(512) void gru_kernel(
    const float* __restrict__ cbias,
    const float* __restrict__ bih, const float* __restrict__ bhh,
    const float* __restrict__ agg_in, const float* __restrict__ h_in,
    float* __restrict__ h_out, float* __restrict__ x_out,
    float* __restrict__ out_extra)
{
    extern __shared__ __half gsm[];
    __half* s_in = gsm;                        // [64][IPAD]
    __half* s_w  = gsm + 64 * IPAD;            // [128][GPAD]
    float*  s_out = (float*)s_w;               // [64][OPAD] (aliases s_w)
    int tid = threadIdx.x;
    int warp = tid >> 5, lane = tid & 31;
    size_t base = (size_t)blockIdx.x * 64;

    // Phase A: input tile [m | h] in fp16. 64 nodes x 128 cols = 8192 elems.
    for (int i = tid; i < 64 * 128; i += 512) {
        int node = i >> 7, c = i & 127;
        size_t n = base + node;
        float v;
        if (c < 64) {
            float cv = g_cnt[n];
            v = fmaxf(agg_in[n * 64 + c] / fmaxf(cv, 1.f) + cbias[c], 0.f);
        } else {
            v = h_in[n * 64 + (c - 64)];
        }
        s_in[node * IPAD + c] = __float2half_rn(v);
    }
    // Stage Wcat: 128 rows x 256 cols = 128 x 32 uint4-chunks = 4096.
    for (int i = tid; i < 4096; i += 512) {
        int row = i >> 5, ch = i & 31;
        *(uint4*)(s_w + row * GPAD + ch * 8) =
            *(const uint4*)(g_wcat + row * 256 + ch * 8);
    }
    __syncthreads();

    // GEMM: M=64, N=256, K=128. wm in {0,32}, wn in {0..224 step 32}.
    int wm = (warp & 1) * 32, wn = (warp >> 1) * 32;
    float acc[2][4][4];
    #pragma unroll
    for (int mi = 0; mi < 2; mi++)
        #pragma unroll
        for (int ni = 0; ni < 4; ni++)
            #pragma unroll
            for (int k = 0; k < 4; k++) acc[mi][ni][k] = 0.f;

    #pragma unroll
    for (int kk = 0; kk < 128; kk += 16) {
        unsigned a[2][4], b[2][4];
        #pragma unroll
        for (int mi = 0; mi < 2; mi++) {
            const __half* ap =
                s_in + (wm + mi * 16 + (lane & 15)) * IPAD + kk + (lane >> 4) * 8;
            unsigned addr = (unsigned)__cvta_generic_to_shared(ap);
            asm volatile("ldmatrix.sync.aligned.m8n8.x4.shared.b16 {%0,%1,%2,%3}, [%4];"
                : "=r"(a[mi][0]), "=r"(a[mi][1]), "=r"(a[mi][2]), "=r"(a[mi][3])
                : "r"(addr));
        }
        #pragma unroll
        for (int nb = 0; nb < 2; nb++) {
            const __half* bp =
                s_w + (kk + (lane & 7) + ((lane >> 3) & 1) * 8) * GPAD
                    + wn + nb * 16 + (lane >> 4) * 8;
            unsigned addr = (unsigned)__cvta_generic_to_shared(bp);
            asm volatile("ldmatrix.sync.aligned.m8n8.x4.trans.shared.b16 {%0,%1,%2,%3}, [%4];"
                : "=r"(b[nb][0]), "=r"(b[nb][1]), "=r"(b[nb][2]), "=r"(b[nb][3])
                : "r"(addr));
        }
        #pragma unroll
        for (int mi = 0; mi < 2; mi++)
            #pragma unroll
            for (int ni = 0; ni < 4; ni++) {
                unsigned b0 = b[ni >> 1][(ni & 1) * 2];
                unsigned b1 = b[ni >> 1][(ni & 1) * 2 + 1];
                asm volatile(
                    "mma.sync.aligned.m16n8k16.row.col.f32.f16.f16.f32 "
                    "{%0,%1,%2,%3}, {%4,%5,%6,%7}, {%8,%9}, {%0,%1,%2,%3};"
                    : "+f"(acc[mi][ni][0]), "+f"(acc[mi][ni][1]),
                      "+f"(acc[mi][ni][2]), "+f"(acc[mi][ni][3])
                    : "r"(a[mi][0]), "r"(a[mi][1]), "r"(a[mi][2]), "r"(a[mi][3]),
                      "r"(b0), "r"(b1));
            }
    }
    __syncthreads();   // all warps done reading s_w before s_out overwrites it

    // Epilogue: acc -> s_out (fp32)
    int g = lane >> 2, t4 = lane & 3;
    #pragma unroll
    for (int mi = 0; mi < 2; mi++) {
        int r0 = wm + mi * 16 + g;
        #pragma unroll
        for (int ni = 0; ni < 4; ni++) {
            int c = wn + ni * 8 + t4 * 2;
            s_out[r0 * OPAD + c]     = acc[mi][ni][0];
            s_out[r0 * OPAD + c + 1] = acc[mi][ni][1];
            s_out[(r0 + 8) * OPAD + c]     = acc[mi][ni][2];
            s_out[(r0 + 8) * OPAD + c + 1] = acc[mi][ni][3];
        }
    }
    __syncthreads();

    // Phase C: activations + state update (h reloaded fp32 from global)
    for (int i = tid; i < 64 * 64; i += 512) {
        int node = i >> 6, f = i & 63;
        size_t n = base + node;
        const float* so = s_out + node * OPAD;
        float r   = 1.f / (1.f + expf(-(so[f]       + bih[f]       + bhh[f])));
        float z   = 1.f / (1.f + expf(-(so[64 + f]  + bih[64 + f]  + bhh[64 + f])));
        float gi2 = so[128 + f] + bih[128 + f];
        float gh2 = so[192 + f] + bhh[128 + f];
        float nn  = tanhf(gi2 + r * gh2);
        float hval = h_in[n * 64 + f];
        float hn = (1.f - z) * nn + z * hval;
        h_out[n * 64 + f] = hn;
        x_out[n * 64 + f] = hn;
        if (out_extra) out_extra[n * 64 + f] = hn;
    }
}

// ---------------- Set2Set LSTM step ----------------
__global__ __launch_bounds__(256) void lstm_kernel(
    const float* __restrict__ wih, const float* __restrict__ whh,
    const float* __restrict__ bih, const float* __restrict__ bhh)
{
    int b = blockIdx.x, j = threadIdx.x;
    __shared__ float sq[128], sh[64], sg[256];
    if (j < 128) sq[j] = g_qstar[b * 128 + j];
    if (j < 64)  sh[j] = g_hs[b * 64 + j];
    __syncthreads();
    float acc = bih[j] + bhh[j];
    const float* wi = wih + (size_t)j * 128;
    #pragma unroll
    for (int k = 0; k < 128; k += 4) {
        float4 w = *(const float4*)(wi + k);
        float4 q = *(const float4*)(sq + k);
        acc = fmaf(w.x, q.x, acc); acc = fmaf(w.y, q.y, acc);
        acc = fmaf(w.z, q.z, acc); acc = fmaf(w.w, q.w, acc);
    }
    const float* wh = whh + (size_t)j * 64;
    #pragma unroll
    for (int k = 0; k < 64; k += 4) {
        float4 w = *(const float4*)(wh + k);
        float4 hv = *(const float4*)(sh + k);
        acc = fmaf(w.x, hv.x, acc); acc = fmaf(w.y, hv.y, acc);
        acc = fmaf(w.z, hv.z, acc); acc = fmaf(w.w, hv.w, acc);
    }
    sg[j] = acc;
    __syncthreads();
    if (j < 64) {
        float ig = 1.f / (1.f + expf(-sg[j]));
        float fg = 1.f / (1.f + expf(-sg[64 + j]));
        float gg = tanhf(sg[128 + j]);
        float og = 1.f / (1.f + expf(-sg[192 + j]));
        float c  = fg * g_cs[b * 64 + j] + ig * gg;
        float hn = og * tanhf(c);
        g_cs[b * 64 + j] = c;
        g_hs[b * 64 + j] = hn;
        g_qstar[b * 128 + j] = hn;
    }
}

// ---------------- Set2Set attention (softmax over sorted segments) ----------------
__global__ __launch_bounds__(128) void attn_kernel(float* __restrict__ dout)
{
    int b = blockIdx.x, tid = threadIdx.x;
    __shared__ float sq[64];
    __shared__ float se[2048];
    __shared__ float red[4];
    if (tid < 64) sq[tid] = g_hs[b * 64 + tid];
    __syncthreads();
    int s = g_off[b], e = g_off[b + 1];
    int cnt = e - s; if (cnt > 2048) cnt = 2048;
    float lmax = -3e38f;
    for (int i = tid; i < cnt; i += 128) {
        const float* xr = g_x + (size_t)(s + i) * DD;
        float acc = 0.f;
        #pragma unroll
        for (int d = 0; d < 64; d += 4) {
            float4 xv = *(const float4*)(xr + d);
            acc = fmaf(xv.x, sq[d], acc);     acc = fmaf(xv.y, sq[d + 1], acc);
            acc = fmaf(xv.z, sq[d + 2], acc); acc = fmaf(xv.w, sq[d + 3], acc);
        }
        se[i] = acc;
        lmax = fmaxf(lmax, acc);
    }
    #pragma unroll
    for (int o = 16; o; o >>= 1) lmax = fmaxf(lmax, __shfl_xor_sync(0xffffffffu, lmax, o));
    if ((tid & 31) == 0) red[tid >> 5] = lmax;
    __syncthreads();
    float M = fmaxf(fmaxf(red[0], red[1]), fmaxf(red[2], red[3]));
    __syncthreads();
    float lsum = 0.f;
    for (int i = tid; i < cnt; i += 128) {
        float v = expf(se[i] - M);
        se[i] = v;
        lsum += v;
    }
    #pragma unroll
    for (int o = 16; o; o >>= 1) lsum += __shfl_xor_sync(0xffffffffu, lsum, o);
    if ((tid & 31) == 0) red[tid >> 5] = lsum;
    __syncthreads();
    float S = red[0] + red[1] + red[2] + red[3];
    float inv = 1.f / (S + 1e-16f);
    if (tid < 64) {
        float rv = 0.f;
        for (int i = 0; i < cnt; i++)
            rv = fmaf(se[i], g_x[(size_t)(s + i) * DD + tid], rv);
        rv *= inv;
        g_qstar[b * 128 + 64 + tid] = rv;
        if (dout) {
            dout[b * 128 + tid] = sq[tid];
            dout[b * 128 + 64 + tid] = rv;
        }
    }
}

// ---------------- launch ----------------
extern "C" void kernel_launch(void* const* d_in, const int* in_sizes, int n_in,
                              void* d_out, int out_size)
{
    const float* node_features = (const float*)d_in[0];
    const float* edge_features = (const float*)d_in[1];
    const int*   edge_index    = (const int*)d_in[2];
    const int*   graph_index   = (const int*)d_in[3];
    const float* lin0_w  = (const float*)d_in[4];
    const float* lin0_b  = (const float*)d_in[5];
    const float* mlp_w1  = (const float*)d_in[6];
    const float* mlp_b1  = (const float*)d_in[7];
    const float* mlp_w2  = (const float*)d_in[8];
    const float* mlp_b2  = (const float*)d_in[9];
    const float* conv_bias = (const float*)d_in[10];
    const float* gru_w_ih = (const float*)d_in[11];
    const float* gru_w_hh = (const float*)d_in[12];
    const float* gru_b_ih = (const float*)d_in[13];
    const float* gru_b_hh = (const float*)d_in[14];
    const float* lstm_w_ih = (const float*)d_in[15];
    const float* lstm_w_hh = (const float*)d_in[16];
    const float* lstm_b_ih = (const float*)d_in[17];
    const float* lstm_b_hh = (const float*)d_in[18];
    float* out = (float*)d_out;
    const int* src = edge_index;
    const int* dst = edge_index + NE;

    // Resolve device-global addresses (host API, allocation-free).
    float *p_x = nullptr, *p_h = nullptr, *p_agg = nullptr;
    cudaGetSymbolAddress((void**)&p_x, g_x);
    cudaGetSymbolAddress((void**)&p_h, g_h);
    cudaGetSymbolAddress((void**)&p_agg, g_agg);

    cudaFuncSetAttribute(wgemm_f16_kernel, cudaFuncAttributeMaxDynamicSharedMemorySize, WG_SMEM);
    cudaFuncSetAttribute(gru_kernel, cudaFuncAttributeMaxDynamicSharedMemorySize, GRU_SMEM);

    h1_kernel<<<NE / 2, 256>>>(edge_features, mlp_w1, mlp_b1);
    lin0_kernel<<<NV / 4, 256>>>(node_features, lin0_w, lin0_b);
    zero_cnt_kernel<<<NV / 256, 256>>>();
    w2cvt_kernel<<<(H1 * D2) / 256, 256>>>(mlp_w2);
    wcat_kernel<<<128, 256>>>(gru_w_ih, gru_w_hh);
    dim3 wg(D2 / 64, NE / 128);
    wgemm_f16_kernel<<<wg, 256, WG_SMEM>>>(mlp_b2);
    count_kernel<<<NE / 256, 256>>>(dst);
    offs_kernel<<<NV / 256, 256>>>(graph_index);

    for (int it = 0; it < 3; it++) {
        zero_agg_kernel<<<(NV * DD) / 256, 256>>>();
        msg_kernel<<<NE / 8, 256>>>(src, dst);
        gru_kernel<<<NV / 64, 512, GRU_SMEM>>>(conv_bias, gru_b_ih, gru_b_hh,
                                               p_agg, p_h, p_h, p_x,
                                               (it == 2) ? (out + NB * 2 * DD) : nullptr);
    }

    zero_s2s_kernel<<<(NB * 2 * DD) / 256, 256>>>();
    for (int t = 0; t < 3; t++) {
        lstm_kernel<<<NB, 256>>>(lstm_w_ih, lstm_w_hh, lstm_b_ih, lstm_b_hh);
        attn_kernel<<<NB, 128>>>((t == 2) ? out : nullptr);
    }
}